// round 6
// baseline (speedup 1.0000x reference)
#include <cuda_runtime.h>
#include <math.h>

#define HEADS 16
#define KVH 8
#define HD 128
#define HDIM 2048
#define GROUPS (HEADS/KVH)
#define MAXB 2
#define MAXS 2048
#define MAXM (MAXB*MAXS)

// ---------------- device scratch (no allocations allowed) ----------------
__device__ double g_wsum[4];
__device__ double g_wabs[4];
__device__ float  g_wscale[4];

__device__ __align__(16) signed char g_sgn0[HDIM*HDIM];
__device__ __align__(16) signed char g_sgn1[KVH*HD*HDIM];
__device__ __align__(16) signed char g_sgn2[KVH*HD*HDIM];
__device__ __align__(16) signed char g_sgn3[HDIM*HDIM];
__device__ __align__(16) signed char g_aq[4][(size_t)MAXM*HDIM];
__device__ float g_as[4][MAXM];
__device__ float g_qb[(size_t)MAXB*HEADS*MAXS*HD];
__device__ float g_kb[(size_t)MAXB*KVH*MAXS*HD];
__device__ float g_vb[(size_t)MAXB*KVH*MAXS*HD];
__device__ float g_ao[(size_t)MAXM*HDIM];

__device__ __forceinline__ signed char* sgn_ptr(int s){
    return (s==0)?g_sgn0:(s==1)?g_sgn1:(s==2)?g_sgn2:g_sgn3;
}

// ---------------- packed fp32x2 helpers (Blackwell f32x2 pipe) ----------------
__device__ __forceinline__ unsigned long long ld2(const float* p){
    return *reinterpret_cast<const unsigned long long*>(p);
}
__device__ __forceinline__ unsigned long long fma2(unsigned long long a,
                                                   unsigned long long b,
                                                   unsigned long long c){
    unsigned long long d;
    asm("fma.rn.f32x2 %0, %1, %2, %3;" : "=l"(d) : "l"(a), "l"(b), "l"(c));
    return d;
}
__device__ __forceinline__ unsigned long long pack2(float x){
    unsigned long long r;
    asm("mov.b64 %0, {%1, %1};" : "=l"(r) : "f"(x));
    return r;
}
__device__ __forceinline__ float lo2(unsigned long long v){
    float a; asm("{ .reg .b32 hi; mov.b64 {%0, hi}, %1; }" : "=f"(a) : "l"(v)); return a;
}
__device__ __forceinline__ float hi2(unsigned long long v){
    float a; asm("{ .reg .b32 lo; mov.b64 {lo, %0}, %1; }" : "=f"(a) : "l"(v)); return a;
}

// ---------------- weight statistics ----------------
__global__ void zero_stats_kernel(){
    if (threadIdx.x < 4){ g_wsum[threadIdx.x]=0.0; g_wabs[threadIdx.x]=0.0; }
}

__global__ void wstats_kernel(const float* __restrict__ W, long n, int slot){
    float s=0.f, a=0.f;
    long stride = (long)gridDim.x*blockDim.x;
    for (long i = blockIdx.x*(long)blockDim.x + threadIdx.x; i<n; i+=stride){
        float w = W[i]; s += w; a += fabsf(w);
    }
    __shared__ float rs[256], ra[256];
    rs[threadIdx.x]=s; ra[threadIdx.x]=a; __syncthreads();
    for (int o=128;o>0;o>>=1){
        if ((int)threadIdx.x<o){ rs[threadIdx.x]+=rs[threadIdx.x+o]; ra[threadIdx.x]+=ra[threadIdx.x+o]; }
        __syncthreads();
    }
    if (threadIdx.x==0){
        atomicAdd(&g_wsum[slot],(double)rs[0]);
        atomicAdd(&g_wabs[slot],(double)ra[0]);
    }
}

__global__ void wsign_kernel(const float* __restrict__ W, long n, int slot){
    float e  = (float)(g_wsum[slot]/(double)n);
    float sc = fmaxf((float)(g_wabs[slot]/(double)n), 1e-8f);
    if (blockIdx.x==0 && threadIdx.x==0) g_wscale[slot]=sc;
    signed char* S8 = sgn_ptr(slot);
    long stride = (long)gridDim.x*blockDim.x;
    for (long i = blockIdx.x*(long)blockDim.x + threadIdx.x; i<n; i+=stride){
        float d = W[i]-e;
        S8[i] = (d>0.f)?(signed char)1:((d<0.f)?(signed char)-1:(signed char)0);
    }
}

// ---------------- rmsnorm + activation quant ----------------
__global__ void act_quant3_kernel(const float* __restrict__ X,
                                  const float* __restrict__ nq,
                                  const float* __restrict__ nk,
                                  const float* __restrict__ nv){
    int m = blockIdx.x, tid = threadIdx.x;
    const float* x = X + (size_t)m*HDIM;
    float v[8]; float ss=0.f;
    #pragma unroll
    for (int i=0;i<8;i++){
        float f = x[tid + i*256];
        f = fminf(fmaxf(f,-100.f),100.f);
        v[i]=f; ss += f*f;
    }
    __shared__ float red[256];
    red[tid]=ss; __syncthreads();
    for (int o=128;o>0;o>>=1){ if (tid<o) red[tid]+=red[tid+o]; __syncthreads(); }
    float var = red[0]*(1.f/(float)HDIM);
    var = fmaxf(var, 1e-5f);
    float rs = 1.f/sqrtf(var + 1e-5f);
    __syncthreads();
    #pragma unroll
    for (int i=0;i<8;i++){
        float b = v[i]*rs;
        v[i] = fminf(fmaxf(b,-10.f),10.f);
    }
    const float* nws[3] = {nq, nk, nv};
    #pragma unroll 1
    for (int slot=0; slot<3; slot++){
        const float* nw = nws[slot];
        float w[8]; float mx=0.f;
        #pragma unroll
        for (int i=0;i<8;i++){
            float t = v[i]*nw[tid+i*256];
            t = fminf(fmaxf(t,-50.f),50.f);
            w[i]=t; mx = fmaxf(mx, fabsf(t));
        }
        red[tid]=mx; __syncthreads();
        for (int o=128;o>0;o>>=1){ if (tid<o) red[tid]=fmaxf(red[tid],red[tid+o]); __syncthreads(); }
        float maxv = fmaxf(red[0], 1e-4f);
        __syncthreads();
        float scale = 127.f/maxv;
        signed char* out8 = g_aq[slot] + (size_t)m*HDIM;
        #pragma unroll
        for (int i=0;i<8;i++){
            int q = __float2int_rn(w[i]*scale);
            q = max(-128, min(127, q));
            out8[tid+i*256] = (signed char)q;
        }
        if (tid==0) g_as[slot][m] = maxv*(1.f/127.f);
    }
}

// single-slot version (slot 3 reads attention output from g_ao)
__global__ void act_quant_kernel(const float* __restrict__ nw, int slot){
    const float* X = g_ao;
    int m = blockIdx.x, tid = threadIdx.x;
    const float* x = X + (size_t)m*HDIM;
    float v[8]; float ss=0.f;
    #pragma unroll
    for (int i=0;i<8;i++){
        float f = x[tid + i*256];
        f = fminf(fmaxf(f,-100.f),100.f);
        v[i]=f; ss += f*f;
    }
    __shared__ float red[256];
    red[tid]=ss; __syncthreads();
    for (int o=128;o>0;o>>=1){ if (tid<o) red[tid]+=red[tid+o]; __syncthreads(); }
    float var = red[0]*(1.f/(float)HDIM);
    var = fmaxf(var, 1e-5f);
    float rs = 1.f/sqrtf(var + 1e-5f);
    __syncthreads();
    float mx=0.f;
    #pragma unroll
    for (int i=0;i<8;i++){
        float b = v[i]*rs;
        b = fminf(fmaxf(b,-10.f),10.f);
        float w = b*nw[tid+i*256];
        w = fminf(fmaxf(w,-50.f),50.f);
        v[i]=w; mx = fmaxf(mx, fabsf(w));
    }
    red[tid]=mx; __syncthreads();
    for (int o=128;o>0;o>>=1){ if (tid<o) red[tid]=fmaxf(red[tid],red[tid+o]); __syncthreads(); }
    float maxv = fmaxf(red[0], 1e-4f);
    float scale = 127.f/maxv;
    signed char* out8 = g_aq[slot] + (size_t)m*HDIM;
    #pragma unroll
    for (int i=0;i<8;i++){
        int q = __float2int_rn(v[i]*scale);
        q = max(-128, min(127, q));
        out8[tid+i*256] = (signed char)q;
    }
    if (tid==0) g_as[slot][m] = maxv*(1.f/127.f);
}

// ---------------- int8 x ternary GEMM via mma.sync (IMMA tensor cores) ----------------
__device__ __forceinline__ void mma_s8(int* c, const int* a, const int* b){
    asm volatile(
        "mma.sync.aligned.m16n8k32.row.col.s32.s8.s8.s32 "
        "{%0,%1,%2,%3}, {%4,%5,%6,%7}, {%8,%9}, {%0,%1,%2,%3};\n"
        : "+r"(c[0]), "+r"(c[1]), "+r"(c[2]), "+r"(c[3])
        : "r"(a[0]), "r"(a[1]), "r"(a[2]), "r"(a[3]), "r"(b[0]), "r"(b[1]));
}

__global__ void __launch_bounds__(256) imma_gemm_kernel(int slot, int N, int S, float* __restrict__ Cext){
    __shared__ int As_s[128*32];   // 128 rows x 32 int32 (KC=128 int8)
    __shared__ int Bs_s[64*32];
    const int KI4 = HDIM/16;       // 128 int4 per row
    int tid = threadIdx.x;
    int m0 = blockIdx.y*128, n0 = blockIdx.x*64;
    const int4* A4 = (const int4*)(g_aq[slot]);
    const int4* B4 = (const int4*)sgn_ptr(slot);

    int warp = tid>>5, lane = tid&31;
    int wm = warp&3, wn = warp>>2;
    int q = lane>>2, t = lane&3;

    int acc[2][4][4];
    #pragma unroll
    for (int mi=0;mi<2;mi++)
        #pragma unroll
        for (int ni=0;ni<4;ni++)
            #pragma unroll
            for (int e=0;e<4;e++) acc[mi][ni][e]=0;

    for (int k0=0; k0<HDIM; k0+=128){
        int kb = k0>>4;
        #pragma unroll
        for (int i=0;i<4;i++){
            int idx = tid + i*256;
            int r = idx>>3, b = idx&7;
            int4 val = A4[(size_t)(m0+r)*KI4 + kb + b];
            ((int4*)As_s)[r*8 + (b ^ (r&7))] = val;
        }
        #pragma unroll
        for (int i=0;i<2;i++){
            int idx = tid + i*256;
            int r = idx>>3, b = idx&7;
            int4 val = B4[(size_t)(n0+r)*KI4 + kb + b];
            ((int4*)Bs_s)[r*8 + (b ^ (r&7))] = val;
        }
        __syncthreads();
        #pragma unroll
        for (int s=0;s<4;s++){
            int a[2][4], bf[4][2];
            #pragma unroll
            for (int mi=0;mi<2;mi++){
                int r0 = wm*32 + mi*16 + q;
                int r1 = r0 + 8;
                a[mi][0] = As_s[r0*32 + ((2*s+0)^(r0&7))*4 + t];
                a[mi][1] = As_s[r1*32 + ((2*s+0)^(r1&7))*4 + t];
                a[mi][2] = As_s[r0*32 + ((2*s+1)^(r0&7))*4 + t];
                a[mi][3] = As_s[r1*32 + ((2*s+1)^(r1&7))*4 + t];
            }
            #pragma unroll
            for (int ni=0;ni<4;ni++){
                int rn = wn*32 + ni*8 + q;
                bf[ni][0] = Bs_s[rn*32 + ((2*s+0)^(rn&7))*4 + t];
                bf[ni][1] = Bs_s[rn*32 + ((2*s+1)^(rn&7))*4 + t];
            }
            #pragma unroll
            for (int mi=0;mi<2;mi++)
                #pragma unroll
                for (int ni=0;ni<4;ni++)
                    mma_s8(acc[mi][ni], a[mi], bf[ni]);
        }
        __syncthreads();
    }

    float ws = g_wscale[slot];
    float* Cq = (slot==0)? g_qb : (slot==1)? g_kb : g_vb;
    int NH = N>>7;
    #pragma unroll
    for (int mi=0;mi<2;mi++){
        #pragma unroll
        for (int h=0;h<2;h++){
            int m = m0 + wm*32 + mi*16 + q + 8*h;
            float fsc = g_as[slot][m]*ws;
            int b_ = m/S, sdx = m - b_*S;
            #pragma unroll
            for (int ni=0;ni<4;ni++){
                #pragma unroll
                for (int e=0;e<2;e++){
                    int n = n0 + wn*32 + ni*8 + t*2 + e;
                    float val = (float)acc[mi][ni][2*h+e]*fsc;
                    if (slot==3){
                        Cext[(size_t)m*N + n] = val;
                    } else {
                        int hh = n>>7, d = n&127;
                        Cq[(((size_t)(b_*NH+hh))*S + sdx)*HD + d] = val;
                    }
                }
            }
        }
    }
}

// ---------------- RoPE (in-place on [B,nh,S,128] buffers) ----------------
__global__ void rope_kernel(int which, int S, long total){
    long idx = blockIdx.x*(long)blockDim.x + threadIdx.x;
    if (idx>=total) return;
    float* buf = which? g_kb : g_qb;
    int i = (int)(idx & 63);
    long row = idx >> 6;
    int s = (int)(row % S);
    size_t base = (size_t)row*HD;
    float inv = powf(10000.f, -((float)i)*(1.f/64.f));
    float fr = (float)s * inv;
    float sn, cs; sincosf(fr,&sn,&cs);
    float x1 = buf[base+i], x2 = buf[base+i+64];
    buf[base+i]    = x1*cs - x2*sn;
    buf[base+i+64] = x2*cs + x1*sn;
}

// ---------------- flash attention (online softmax, fp32, f32x2 packed) ----------------
// 128x128 tiles, 256 threads, 8x8 score tile/thread.
// smem: Qs[128][130] row-major; Ks buffer holds K TRANSPOSED ([k][seq], pitch 130)
// during QK, then V row-major ([seq][dim]) during PV. Ss[128][130] scores.
__global__ void __launch_bounds__(256,1) flash_kernel(const float* __restrict__ mask, int S){
    extern __shared__ float sh[];
    float* Qs = sh;               // 128*130
    float* Ks = Qs + 128*130;     // 128*130
    float* Ss = Ks + 128*130;     // 128*130
    int tid = threadIdx.x;
    int tq = blockIdx.x, bh = blockIdx.y;
    int b = bh/HEADS, h = bh%HEADS, hk = h/GROUPS;
    int sq0 = tq*128;
    const float* Qg = g_qb + (((size_t)bh)*S + sq0)*HD;
    const float* Kg = g_kb + ((size_t)(b*KVH+hk)*S)*HD;
    const float* Vg = g_vb + ((size_t)(b*KVH+hk)*S)*HD;

    for (int e=tid; e<128*HD; e+=256) Qs[(e>>7)*130 + (e&127)] = Qg[e];

    int rg = tid>>4, cg = tid&15, r0 = rg*8;
    int cb = 2*cg;                           // base column (pairs at cb+32j)
    float2 o2[8][4];
    #pragma unroll
    for (int i=0;i<8;i++)
        #pragma unroll
        for (int j=0;j<4;j++){ o2[i][j].x=0.f; o2[i][j].y=0.f; }
    float mreg[8], lreg[8];
    #pragma unroll
    for (int i=0;i<8;i++){ mreg[i] = __int_as_float(0xff800000); lreg[i]=0.f; }
    const float sc = 0.08838834764831845f;   // 1/sqrt(128)
    __syncthreads();

    int NT = S/128;
    for (int kt=0; kt<NT; kt++){
        // load K tile transposed: Ks[k][seq]
        const float* Kt = Kg + (size_t)kt*128*HD;
        for (int e=tid; e<128*HD; e+=256){
            int row = e>>7, k = e&127;
            Ks[k*130 + row] = Kt[e];
        }
        __syncthreads();

        // --- QK^T: f32x2 over adjacent score columns ---
        unsigned long long acc[8][4];
        #pragma unroll
        for (int i=0;i<8;i++)
            #pragma unroll
            for (int j=0;j<4;j++) acc[i][j]=0ull;
        #pragma unroll 4
        for (int k=0;k<HD;k++){
            const float* kr = Ks + k*130 + cb;
            unsigned long long b0 = ld2(kr);
            unsigned long long b1 = ld2(kr+32);
            unsigned long long b2 = ld2(kr+64);
            unsigned long long b3 = ld2(kr+96);
            #pragma unroll
            for (int i=0;i<8;i++){
                unsigned long long ai = pack2(Qs[(r0+i)*130 + k]);
                acc[i][0]=fma2(ai,b0,acc[i][0]);
                acc[i][1]=fma2(ai,b1,acc[i][1]);
                acc[i][2]=fma2(ai,b2,acc[i][2]);
                acc[i][3]=fma2(ai,b3,acc[i][3]);
            }
        }

        float fac[8];
        #pragma unroll
        for (int i=0;i<8;i++){
            const float* mrow = mask + (size_t)(sq0+r0+i)*S + (size_t)kt*128 + cb;
            float s8[8];
            #pragma unroll
            for (int j=0;j<4;j++){
                s8[2*j]   = lo2(acc[i][j])*sc + mrow[32*j];
                s8[2*j+1] = hi2(acc[i][j])*sc + mrow[32*j+1];
            }
            float mx = s8[0];
            #pragma unroll
            for (int jj=1;jj<8;jj++) mx = fmaxf(mx, s8[jj]);
            mx = fmaxf(mx,__shfl_xor_sync(0xffffffffu,mx,1,16));
            mx = fmaxf(mx,__shfl_xor_sync(0xffffffffu,mx,2,16));
            mx = fmaxf(mx,__shfl_xor_sync(0xffffffffu,mx,4,16));
            mx = fmaxf(mx,__shfl_xor_sync(0xffffffffu,mx,8,16));
            float mn = fmaxf(mreg[i], mx);
            float su=0.f;
            #pragma unroll
            for (int jj=0;jj<8;jj++){ float p = expf(s8[jj]-mn); s8[jj]=p; su+=p; }
            su += __shfl_xor_sync(0xffffffffu,su,1,16);
            su += __shfl_xor_sync(0xffffffffu,su,2,16);
            su += __shfl_xor_sync(0xffffffffu,su,4,16);
            su += __shfl_xor_sync(0xffffffffu,su,8,16);
            float f = expf(mreg[i]-mn);
            lreg[i] = lreg[i]*f + su;
            mreg[i] = mn;
            fac[i]  = f;
            float* srow = Ss + (size_t)(r0+i)*130 + cb;
            #pragma unroll
            for (int j=0;j<4;j++){
                float2 pv; pv.x = s8[2*j]; pv.y = s8[2*j+1];
                *(float2*)(srow + 32*j) = pv;
            }
        }
        __syncthreads();

        // load V tile row-major into Ks, rescale o2
        const float* Vt = Vg + (size_t)kt*128*HD;
        for (int e=tid; e<128*HD; e+=256) Ks[(e>>7)*130 + (e&127)] = Vt[e];
        #pragma unroll
        for (int i=0;i<8;i++){
            float f = fac[i];
            #pragma unroll
            for (int j=0;j<4;j++){ o2[i][j].x*=f; o2[i][j].y*=f; }
        }
        __syncthreads();

        // --- P @ V: f32x2 over output dims ---
        #pragma unroll 2
        for (int kk=0;kk<128;kk++){
            const float* vr = Ks + kk*130 + cb;
            unsigned long long v0 = ld2(vr);
            unsigned long long v1 = ld2(vr+32);
            unsigned long long v2 = ld2(vr+64);
            unsigned long long v3 = ld2(vr+96);
            #pragma unroll
            for (int i=0;i<8;i++){
                unsigned long long pi = pack2(Ss[(size_t)(r0+i)*130 + kk]);
                unsigned long long* op = (unsigned long long*)&o2[i][0];
                op[0] = fma2(pi, v0, op[0]);
                op[1] = fma2(pi, v1, op[1]);
                op[2] = fma2(pi, v2, op[2]);
                op[3] = fma2(pi, v3, op[3]);
            }
        }
        __syncthreads();
    }

    #pragma unroll
    for (int i=0;i<8;i++){
        float inv = 1.f/lreg[i];
        size_t rowbase = ((size_t)b*S + (size_t)(sq0+r0+i))*HDIM + (size_t)h*HD;
        #pragma unroll
        for (int j=0;j<4;j++){
            float2 v = o2[i][j];
            v.x*=inv; v.y*=inv;
            *(float2*)&g_ao[rowbase + cb + 32*j] = v;
        }
    }
}

// ---------------- launch ----------------
extern "C" void kernel_launch(void* const* d_in, const int* in_sizes, int n_in,
                              void* d_out, int out_size){
    const float* hidden = (const float*)d_in[0];
    const float* mask   = (const float*)d_in[1];
    const float* wq     = (const float*)d_in[2];
    const float* wk     = (const float*)d_in[3];
    const float* wv     = (const float*)d_in[4];
    const float* wo     = (const float*)d_in[5];
    const float* nq     = (const float*)d_in[6];
    const float* nk     = (const float*)d_in[7];
    const float* nv     = (const float*)d_in[8];
    const float* no_    = (const float*)d_in[9];
    float* out = (float*)d_out;

    int S = MAXS;
    {
        long ms = in_sizes[1];
        int s = (int)(sqrt((double)ms)+0.5);
        if ((long)s*s == ms) S = s;
    }
    int M = in_sizes[0]/HDIM;   // B*S rows
    int B = M/S;

    long nw_big   = (long)HDIM*HDIM;      // wq, wo
    long nw_small = (long)KVH*HD*HDIM;    // wk, wv

    zero_stats_kernel<<<1,32>>>();
    wstats_kernel<<<512,256>>>(wq, nw_big,   0);
    wstats_kernel<<<512,256>>>(wk, nw_small, 1);
    wstats_kernel<<<512,256>>>(wv, nw_small, 2);
    wstats_kernel<<<512,256>>>(wo, nw_big,   3);
    wsign_kernel<<<2048,256>>>(wq, nw_big,   0);
    wsign_kernel<<<1024,256>>>(wk, nw_small, 1);
    wsign_kernel<<<1024,256>>>(wv, nw_small, 2);
    wsign_kernel<<<2048,256>>>(wo, nw_big,   3);

    act_quant3_kernel<<<M,256>>>(hidden, nq, nk, nv);

    imma_gemm_kernel<<<dim3(HDIM/64,     M/128),256>>>(0, HDIM,   S, nullptr);
    imma_gemm_kernel<<<dim3((KVH*HD)/64, M/128),256>>>(1, KVH*HD, S, nullptr);
    imma_gemm_kernel<<<dim3((KVH*HD)/64, M/128),256>>>(2, KVH*HD, S, nullptr);

    long tq = (long)B*HEADS*S*64;
    rope_kernel<<<(unsigned)((tq+255)/256),256>>>(0, S, tq);
    long tk = (long)B*KVH*S*64;
    rope_kernel<<<(unsigned)((tk+255)/256),256>>>(1, S, tk);

    const int FLASH_SMEM = 128*130*3*4;  // 199680 bytes
    cudaFuncSetAttribute(flash_kernel, cudaFuncAttributeMaxDynamicSharedMemorySize, FLASH_SMEM);
    flash_kernel<<<dim3(S/128, B*HEADS),256,FLASH_SMEM>>>(mask, S);

    act_quant_kernel<<<M,256>>>(no_, 3);
    imma_gemm_kernel<<<dim3(HDIM/64, M/128),256>>>(3, HDIM, S, out);
}

// round 7
// speedup vs baseline: 1.2102x; 1.2102x over previous
#include <cuda_runtime.h>
#include <math.h>

#define HEADS 16
#define KVH 8
#define HD 128
#define HDIM 2048
#define GROUPS (HEADS/KVH)
#define MAXB 2
#define MAXS 2048
#define MAXM (MAXB*MAXS)

#define NW_BIG   ((long)HDIM*HDIM)
#define NW_SMALL ((long)KVH*HD*HDIM)
#define STATS_BLOCKS 512

// ---------------- device scratch (no allocations allowed) ----------------
__device__ float g_ps[4][STATS_BLOCKS];
__device__ float g_pa[4][STATS_BLOCKS];
__device__ float g_wscale[4];

__device__ __align__(16) signed char g_sgn0[HDIM*HDIM];
__device__ __align__(16) signed char g_sgn1[KVH*HD*HDIM];
__device__ __align__(16) signed char g_sgn2[KVH*HD*HDIM];
__device__ __align__(16) signed char g_sgn3[HDIM*HDIM];
__device__ __align__(16) signed char g_aq[4][(size_t)MAXM*HDIM];
__device__ float g_as[4][MAXM];
__device__ float g_qb[(size_t)MAXB*HEADS*MAXS*HD];
__device__ float g_kb[(size_t)MAXB*KVH*MAXS*HD];
__device__ float g_vb[(size_t)MAXB*KVH*MAXS*HD];
__device__ float g_ao[(size_t)MAXM*HDIM];

__device__ __forceinline__ signed char* sgn_ptr(int s){
    return (s==0)?g_sgn0:(s==1)?g_sgn1:(s==2)?g_sgn2:g_sgn3;
}

// ---------------- packed fp32x2 helpers (Blackwell f32x2 pipe) ----------------
__device__ __forceinline__ unsigned long long ld2(const float* p){
    return *reinterpret_cast<const unsigned long long*>(p);
}
__device__ __forceinline__ unsigned long long fma2(unsigned long long a,
                                                   unsigned long long b,
                                                   unsigned long long c){
    unsigned long long d;
    asm("fma.rn.f32x2 %0, %1, %2, %3;" : "=l"(d) : "l"(a), "l"(b), "l"(c));
    return d;
}
__device__ __forceinline__ unsigned long long pack2(float x){
    unsigned long long r;
    asm("mov.b64 %0, {%1, %1};" : "=l"(r) : "f"(x));
    return r;
}
__device__ __forceinline__ float lo2(unsigned long long v){
    float a; asm("{ .reg .b32 hi; mov.b64 {%0, hi}, %1; }" : "=f"(a) : "l"(v)); return a;
}
__device__ __forceinline__ float hi2(unsigned long long v){
    float a; asm("{ .reg .b32 lo; mov.b64 {lo, %0}, %1; }" : "=f"(a) : "l"(v)); return a;
}

// ---------------- weight statistics: partials, no atomics ----------------
// grid (STATS_BLOCKS, 4); y = slot
__global__ void wstats_all_kernel(const float* __restrict__ wq, const float* __restrict__ wk,
                                  const float* __restrict__ wv, const float* __restrict__ wo){
    int slot = blockIdx.y;
    const float* W = (slot==0)?wq:(slot==1)?wk:(slot==2)?wv:wo;
    long n = (slot==0 || slot==3)? NW_BIG : NW_SMALL;
    float s=0.f, a=0.f;
    long stride = (long)gridDim.x*blockDim.x;
    for (long i = blockIdx.x*(long)blockDim.x + threadIdx.x; i<n; i+=stride){
        float w = W[i]; s += w; a += fabsf(w);
    }
    __shared__ float rs[256], ra[256];
    rs[threadIdx.x]=s; ra[threadIdx.x]=a; __syncthreads();
    for (int o=128;o>0;o>>=1){
        if ((int)threadIdx.x<o){ rs[threadIdx.x]+=rs[threadIdx.x+o]; ra[threadIdx.x]+=ra[threadIdx.x+o]; }
        __syncthreads();
    }
    if (threadIdx.x==0){
        g_ps[slot][blockIdx.x]=rs[0];
        g_pa[slot][blockIdx.x]=ra[0];
    }
}

// grid (1024, 4); y = slot. Each block reduces the 512 partials itself (L2-cached).
__global__ void wsign_all_kernel(const float* __restrict__ wq, const float* __restrict__ wk,
                                 const float* __restrict__ wv, const float* __restrict__ wo){
    int slot = blockIdx.y;
    const float* W = (slot==0)?wq:(slot==1)?wk:(slot==2)?wv:wo;
    long n = (slot==0 || slot==3)? NW_BIG : NW_SMALL;
    __shared__ float rs[256], ra[256];
    {
        float s = g_ps[slot][threadIdx.x] + g_ps[slot][threadIdx.x+256];
        float a = g_pa[slot][threadIdx.x] + g_pa[slot][threadIdx.x+256];
        rs[threadIdx.x]=s; ra[threadIdx.x]=a; __syncthreads();
        for (int o=128;o>0;o>>=1){
            if ((int)threadIdx.x<o){ rs[threadIdx.x]+=rs[threadIdx.x+o]; ra[threadIdx.x]+=ra[threadIdx.x+o]; }
            __syncthreads();
        }
    }
    float e  = rs[0]/(float)n;
    float sc = fmaxf(ra[0]/(float)n, 1e-8f);
    if (blockIdx.x==0 && threadIdx.x==0) g_wscale[slot]=sc;
    signed char* S8 = sgn_ptr(slot);
    long stride = (long)gridDim.x*blockDim.x;
    for (long i = blockIdx.x*(long)blockDim.x + threadIdx.x; i<n; i+=stride){
        float d = W[i]-e;
        S8[i] = (d>0.f)?(signed char)1:((d<0.f)?(signed char)-1:(signed char)0);
    }
}

// ---------------- rmsnorm + activation quant ----------------
__global__ void act_quant3_kernel(const float* __restrict__ X,
                                  const float* __restrict__ nq,
                                  const float* __restrict__ nk,
                                  const float* __restrict__ nv){
    int m = blockIdx.x, tid = threadIdx.x;
    const float* x = X + (size_t)m*HDIM;
    float v[8]; float ss=0.f;
    #pragma unroll
    for (int i=0;i<8;i++){
        float f = x[tid + i*256];
        f = fminf(fmaxf(f,-100.f),100.f);
        v[i]=f; ss += f*f;
    }
    __shared__ float red[256];
    red[tid]=ss; __syncthreads();
    for (int o=128;o>0;o>>=1){ if (tid<o) red[tid]+=red[tid+o]; __syncthreads(); }
    float var = red[0]*(1.f/(float)HDIM);
    var = fmaxf(var, 1e-5f);
    float rs = 1.f/sqrtf(var + 1e-5f);
    __syncthreads();
    #pragma unroll
    for (int i=0;i<8;i++){
        float b = v[i]*rs;
        v[i] = fminf(fmaxf(b,-10.f),10.f);
    }
    const float* nws[3] = {nq, nk, nv};
    #pragma unroll 1
    for (int slot=0; slot<3; slot++){
        const float* nw = nws[slot];
        float w[8]; float mx=0.f;
        #pragma unroll
        for (int i=0;i<8;i++){
            float t = v[i]*nw[tid+i*256];
            t = fminf(fmaxf(t,-50.f),50.f);
            w[i]=t; mx = fmaxf(mx, fabsf(t));
        }
        red[tid]=mx; __syncthreads();
        for (int o=128;o>0;o>>=1){ if (tid<o) red[tid]=fmaxf(red[tid],red[tid+o]); __syncthreads(); }
        float maxv = fmaxf(red[0], 1e-4f);
        __syncthreads();
        float scale = 127.f/maxv;
        signed char* out8 = g_aq[slot] + (size_t)m*HDIM;
        #pragma unroll
        for (int i=0;i<8;i++){
            int q = __float2int_rn(w[i]*scale);
            q = max(-128, min(127, q));
            out8[tid+i*256] = (signed char)q;
        }
        if (tid==0) g_as[slot][m] = maxv*(1.f/127.f);
    }
}

// single-slot version (slot 3 reads attention output from g_ao)
__global__ void act_quant_kernel(const float* __restrict__ nw, int slot){
    const float* X = g_ao;
    int m = blockIdx.x, tid = threadIdx.x;
    const float* x = X + (size_t)m*HDIM;
    float v[8]; float ss=0.f;
    #pragma unroll
    for (int i=0;i<8;i++){
        float f = x[tid + i*256];
        f = fminf(fmaxf(f,-100.f),100.f);
        v[i]=f; ss += f*f;
    }
    __shared__ float red[256];
    red[tid]=ss; __syncthreads();
    for (int o=128;o>0;o>>=1){ if (tid<o) red[tid]+=red[tid+o]; __syncthreads(); }
    float var = red[0]*(1.f/(float)HDIM);
    var = fmaxf(var, 1e-5f);
    float rs = 1.f/sqrtf(var + 1e-5f);
    __syncthreads();
    float mx=0.f;
    #pragma unroll
    for (int i=0;i<8;i++){
        float b = v[i]*rs;
        b = fminf(fmaxf(b,-10.f),10.f);
        float w = b*nw[tid+i*256];
        w = fminf(fmaxf(w,-50.f),50.f);
        v[i]=w; mx = fmaxf(mx, fabsf(w));
    }
    red[tid]=mx; __syncthreads();
    for (int o=128;o>0;o>>=1){ if (tid<o) red[tid]=fmaxf(red[tid],red[tid+o]); __syncthreads(); }
    float maxv = fmaxf(red[0], 1e-4f);
    float scale = 127.f/maxv;
    signed char* out8 = g_aq[slot] + (size_t)m*HDIM;
    #pragma unroll
    for (int i=0;i<8;i++){
        int q = __float2int_rn(v[i]*scale);
        q = max(-128, min(127, q));
        out8[tid+i*256] = (signed char)q;
    }
    if (tid==0) g_as[slot][m] = maxv*(1.f/127.f);
}

// ---------------- int8 x ternary GEMM via mma.sync (IMMA tensor cores) ----------------
__device__ __forceinline__ void mma_s8(int* c, const int* a, const int* b){
    asm volatile(
        "mma.sync.aligned.m16n8k32.row.col.s32.s8.s8.s32 "
        "{%0,%1,%2,%3}, {%4,%5,%6,%7}, {%8,%9}, {%0,%1,%2,%3};\n"
        : "+r"(c[0]), "+r"(c[1]), "+r"(c[2]), "+r"(c[3])
        : "r"(a[0]), "r"(a[1]), "r"(a[2]), "r"(a[3]), "r"(b[0]), "r"(b[1]));
}

__device__ __forceinline__ void gemm_body(int slot, int N, int S, float* __restrict__ Cext,
                                          int m0, int n0){
    __shared__ int As_s[128*32];   // 128 rows x 32 int32 (KC=128 int8)
    __shared__ int Bs_s[64*32];
    const int KI4 = HDIM/16;       // 128 int4 per row
    int tid = threadIdx.x;
    const int4* A4 = (const int4*)(g_aq[slot]);
    const int4* B4 = (const int4*)sgn_ptr(slot);

    int warp = tid>>5, lane = tid&31;
    int wm = warp&3, wn = warp>>2;
    int q = lane>>2, t = lane&3;

    int acc[2][4][4];
    #pragma unroll
    for (int mi=0;mi<2;mi++)
        #pragma unroll
        for (int ni=0;ni<4;ni++)
            #pragma unroll
            for (int e=0;e<4;e++) acc[mi][ni][e]=0;

    for (int k0=0; k0<HDIM; k0+=128){
        int kb = k0>>4;
        #pragma unroll
        for (int i=0;i<4;i++){
            int idx = tid + i*256;
            int r = idx>>3, b = idx&7;
            int4 val = A4[(size_t)(m0+r)*KI4 + kb + b];
            ((int4*)As_s)[r*8 + (b ^ (r&7))] = val;
        }
        #pragma unroll
        for (int i=0;i<2;i++){
            int idx = tid + i*256;
            int r = idx>>3, b = idx&7;
            int4 val = B4[(size_t)(n0+r)*KI4 + kb + b];
            ((int4*)Bs_s)[r*8 + (b ^ (r&7))] = val;
        }
        __syncthreads();
        #pragma unroll
        for (int s=0;s<4;s++){
            int a[2][4], bf[4][2];
            #pragma unroll
            for (int mi=0;mi<2;mi++){
                int r0 = wm*32 + mi*16 + q;
                int r1 = r0 + 8;
                a[mi][0] = As_s[r0*32 + ((2*s+0)^(r0&7))*4 + t];
                a[mi][1] = As_s[r1*32 + ((2*s+0)^(r1&7))*4 + t];
                a[mi][2] = As_s[r0*32 + ((2*s+1)^(r0&7))*4 + t];
                a[mi][3] = As_s[r1*32 + ((2*s+1)^(r1&7))*4 + t];
            }
            #pragma unroll
            for (int ni=0;ni<4;ni++){
                int rn = wn*32 + ni*8 + q;
                bf[ni][0] = Bs_s[rn*32 + ((2*s+0)^(rn&7))*4 + t];
                bf[ni][1] = Bs_s[rn*32 + ((2*s+1)^(rn&7))*4 + t];
            }
            #pragma unroll
            for (int mi=0;mi<2;mi++)
                #pragma unroll
                for (int ni=0;ni<4;ni++)
                    mma_s8(acc[mi][ni], a[mi], bf[ni]);
        }
        __syncthreads();
    }

    float ws = g_wscale[slot];
    float* Cq = (slot==0)? g_qb : (slot==1)? g_kb : g_vb;
    int NH = N>>7;
    #pragma unroll
    for (int mi=0;mi<2;mi++){
        #pragma unroll
        for (int h=0;h<2;h++){
            int m = m0 + wm*32 + mi*16 + q + 8*h;
            float fsc = g_as[slot][m]*ws;
            int b_ = m/S, sdx = m - b_*S;
            #pragma unroll
            for (int ni=0;ni<4;ni++){
                #pragma unroll
                for (int e=0;e<2;e++){
                    int n = n0 + wn*32 + ni*8 + t*2 + e;
                    float val = (float)acc[mi][ni][2*h+e]*fsc;
                    if (slot==3){
                        Cext[(size_t)m*N + n] = val;
                    } else {
                        int hh = n>>7, d = n&127;
                        Cq[(((size_t)(b_*NH+hh))*S + sdx)*HD + d] = val;
                    }
                }
            }
        }
    }
}

// fused q/k/v projection: grid (32, M/128, 3); z = slot; slots 1,2 use only x<16
__global__ void __launch_bounds__(256) imma_qkv_kernel(int S){
    int slot = blockIdx.z;
    int N = (slot==0)? HDIM : KVH*HD;
    if (slot>0 && (int)blockIdx.x >= N/64) return;
    gemm_body(slot, N, S, nullptr, blockIdx.y*128, blockIdx.x*64);
}

__global__ void __launch_bounds__(256) imma_o_kernel(int S, float* __restrict__ Cext){
    gemm_body(3, HDIM, S, Cext, blockIdx.y*128, blockIdx.x*64);
}

// ---------------- RoPE (q and k fused, in-place) ----------------
__global__ void rope_all_kernel(int S, long tq, long total){
    long idx = blockIdx.x*(long)blockDim.x + threadIdx.x;
    if (idx>=total) return;
    float* buf; long lidx;
    if (idx < tq){ buf = g_qb; lidx = idx; }
    else         { buf = g_kb; lidx = idx - tq; }
    int i = (int)(lidx & 63);
    long row = lidx >> 6;
    int s = (int)(row % S);
    size_t base = (size_t)row*HD;
    float inv = powf(10000.f, -((float)i)*(1.f/64.f));
    float fr = (float)s * inv;
    float sn, cs; sincosf(fr,&sn,&cs);
    float x1 = buf[base+i], x2 = buf[base+i+64];
    buf[base+i]    = x1*cs - x2*sn;
    buf[base+i+64] = x2*cs + x1*sn;
}

// ---------------- flash attention (online softmax, fp32, f32x2 packed) ----------------
// grid: (S/64, B*HEADS), 256 threads. Shared: Qs[64][130] Ks[64][130] Ss[64][65]
__global__ void __launch_bounds__(256,2) flash_kernel(const float* __restrict__ mask, int S){
    extern __shared__ float sh[];
    float* Qs = sh;                  // 64*130
    float* Ks = Qs + 64*130;         // 64*130
    float* Ss = Ks + 64*130;         // 64*65
    int tid = threadIdx.x;
    int tq = blockIdx.x, bh = blockIdx.y;
    int b = bh/HEADS, h = bh%HEADS, hk = h/GROUPS;
    int sq0 = tq*64;
    const float* Qg = g_qb + (((size_t)bh)*S + sq0)*HD;
    const float* Kg = g_kb + ((size_t)(b*KVH+hk)*S)*HD;
    const float* Vg = g_vb + ((size_t)(b*KVH+hk)*S)*HD;

    for (int e=tid; e<64*HD; e+=256) Qs[(e>>7)*130 + (e&127)] = Qg[e];

    int g = tid>>4, c0 = tid&15, r0 = g*4;
    float2 o2[4][4];
    #pragma unroll
    for (int i=0;i<4;i++)
        #pragma unroll
        for (int j=0;j<4;j++){ o2[i][j].x=0.f; o2[i][j].y=0.f; }
    float mreg[4], lreg[4];
    #pragma unroll
    for (int i=0;i<4;i++){ mreg[i] = __int_as_float(0xff800000); lreg[i]=0.f; }
    const float sc = 0.08838834764831845f;  // 1/sqrt(128)
    __syncthreads();

    int NT = S/64;
    for (int kt=0; kt<NT; kt++){
        const float* Kt = Kg + (size_t)kt*64*HD;
        for (int e=tid; e<64*HD; e+=256) Ks[(e>>7)*130 + (e&127)] = Kt[e];
        __syncthreads();

        // --- QK^T with packed f32x2 over k ---
        unsigned long long acc2[4][4];
        #pragma unroll
        for (int i=0;i<4;i++)
            #pragma unroll
            for (int j=0;j<4;j++) acc2[i][j]=0ull;
        #pragma unroll 8
        for (int k=0;k<HD;k+=2){
            unsigned long long a0 = ld2(&Qs[(r0+0)*130+k]);
            unsigned long long a1 = ld2(&Qs[(r0+1)*130+k]);
            unsigned long long a2 = ld2(&Qs[(r0+2)*130+k]);
            unsigned long long a3 = ld2(&Qs[(r0+3)*130+k]);
            unsigned long long b0 = ld2(&Ks[(c0+ 0)*130+k]);
            unsigned long long b1 = ld2(&Ks[(c0+16)*130+k]);
            unsigned long long b2 = ld2(&Ks[(c0+32)*130+k]);
            unsigned long long b3 = ld2(&Ks[(c0+48)*130+k]);
            acc2[0][0]=fma2(a0,b0,acc2[0][0]); acc2[0][1]=fma2(a0,b1,acc2[0][1]);
            acc2[0][2]=fma2(a0,b2,acc2[0][2]); acc2[0][3]=fma2(a0,b3,acc2[0][3]);
            acc2[1][0]=fma2(a1,b0,acc2[1][0]); acc2[1][1]=fma2(a1,b1,acc2[1][1]);
            acc2[1][2]=fma2(a1,b2,acc2[1][2]); acc2[1][3]=fma2(a1,b3,acc2[1][3]);
            acc2[2][0]=fma2(a2,b0,acc2[2][0]); acc2[2][1]=fma2(a2,b1,acc2[2][1]);
            acc2[2][2]=fma2(a2,b2,acc2[2][2]); acc2[2][3]=fma2(a2,b3,acc2[2][3]);
            acc2[3][0]=fma2(a3,b0,acc2[3][0]); acc2[3][1]=fma2(a3,b1,acc2[3][1]);
            acc2[3][2]=fma2(a3,b2,acc2[3][2]); acc2[3][3]=fma2(a3,b3,acc2[3][3]);
        }

        float fac[4];
        #pragma unroll
        for (int i=0;i<4;i++){
            float s4[4];
            #pragma unroll
            for (int j=0;j<4;j++) s4[j] = lo2(acc2[i][j]) + hi2(acc2[i][j]);
            const float* mrow = mask + (size_t)(sq0+r0+i)*S + (size_t)kt*64;
            #pragma unroll
            for (int j=0;j<4;j++) s4[j] = s4[j]*sc + mrow[c0+16*j];
            float mx = fmaxf(fmaxf(s4[0],s4[1]),fmaxf(s4[2],s4[3]));
            mx = fmaxf(mx,__shfl_xor_sync(0xffffffffu,mx,1,16));
            mx = fmaxf(mx,__shfl_xor_sync(0xffffffffu,mx,2,16));
            mx = fmaxf(mx,__shfl_xor_sync(0xffffffffu,mx,4,16));
            mx = fmaxf(mx,__shfl_xor_sync(0xffffffffu,mx,8,16));
            float mn = fmaxf(mreg[i], mx);
            float su=0.f;
            #pragma unroll
            for (int j=0;j<4;j++){ float p = __expf(s4[j]-mn); s4[j]=p; su+=p; }
            su += __shfl_xor_sync(0xffffffffu,su,1,16);
            su += __shfl_xor_sync(0xffffffffu,su,2,16);
            su += __shfl_xor_sync(0xffffffffu,su,4,16);
            su += __shfl_xor_sync(0xffffffffu,su,8,16);
            float f = __expf(mreg[i]-mn);
            lreg[i] = lreg[i]*f + su;
            mreg[i] = mn;
            fac[i]  = f;
            #pragma unroll
            for (int j=0;j<4;j++) Ss[(r0+i)*65 + c0+16*j] = s4[j];
        }
        __syncthreads();

        const float* Vt = Vg + (size_t)kt*64*HD;
        for (int e=tid; e<64*HD; e+=256) Ks[(e>>7)*130 + (e&127)] = Vt[e];
        #pragma unroll
        for (int i=0;i<4;i++){
            float f = fac[i];
            #pragma unroll
            for (int j=0;j<4;j++){ o2[i][j].x*=f; o2[i][j].y*=f; }
        }
        __syncthreads();

        // --- P @ V with packed f32x2 over output columns ---
        #pragma unroll 4
        for (int kk=0;kk<64;kk++){
            unsigned long long p0 = pack2(Ss[(r0+0)*65+kk]);
            unsigned long long p1 = pack2(Ss[(r0+1)*65+kk]);
            unsigned long long p2 = pack2(Ss[(r0+2)*65+kk]);
            unsigned long long p3 = pack2(Ss[(r0+3)*65+kk]);
            #pragma unroll
            for (int j=0;j<4;j++){
                unsigned long long vv = ld2(&Ks[kk*130 + 2*(c0+16*j)]);
                *(unsigned long long*)&o2[0][j] = fma2(p0, vv, *(unsigned long long*)&o2[0][j]);
                *(unsigned long long*)&o2[1][j] = fma2(p1, vv, *(unsigned long long*)&o2[1][j]);
                *(unsigned long long*)&o2[2][j] = fma2(p2, vv, *(unsigned long long*)&o2[2][j]);
                *(unsigned long long*)&o2[3][j] = fma2(p3, vv, *(unsigned long long*)&o2[3][j]);
            }
        }
        __syncthreads();
    }

    #pragma unroll
    for (int i=0;i<4;i++){
        float inv = 1.f/lreg[i];
        size_t rowbase = ((size_t)b*S + (size_t)(sq0+r0+i))*HDIM + (size_t)h*HD;
        #pragma unroll
        for (int j=0;j<4;j++){
            float2 v = o2[i][j];
            v.x*=inv; v.y*=inv;
            *(float2*)&g_ao[rowbase + 2*(c0+16*j)] = v;
        }
    }
}

// ---------------- launch ----------------
extern "C" void kernel_launch(void* const* d_in, const int* in_sizes, int n_in,
                              void* d_out, int out_size){
    const float* hidden = (const float*)d_in[0];
    const float* mask   = (const float*)d_in[1];
    const float* wq     = (const float*)d_in[2];
    const float* wk     = (const float*)d_in[3];
    const float* wv     = (const float*)d_in[4];
    const float* wo     = (const float*)d_in[5];
    const float* nq     = (const float*)d_in[6];
    const float* nk     = (const float*)d_in[7];
    const float* nv     = (const float*)d_in[8];
    const float* no_    = (const float*)d_in[9];
    float* out = (float*)d_out;

    int S = MAXS;
    {
        long ms = in_sizes[1];
        int s = (int)(sqrt((double)ms)+0.5);
        if ((long)s*s == ms) S = s;
    }
    int M = in_sizes[0]/HDIM;   // B*S rows
    int B = M/S;

    // launches ordered so ncu (-s 5 -c 1) captures flash_kernel (launch #6)
    wstats_all_kernel<<<dim3(STATS_BLOCKS,4),256>>>(wq,wk,wv,wo);          // 1
    wsign_all_kernel<<<dim3(1024,4),256>>>(wq,wk,wv,wo);                    // 2
    act_quant3_kernel<<<M,256>>>(hidden, nq, nk, nv);                       // 3
    imma_qkv_kernel<<<dim3(HDIM/64, M/128, 3),256>>>(S);                    // 4

    long tq = (long)B*HEADS*S*64;
    long tk = (long)B*KVH*S*64;
    rope_all_kernel<<<(unsigned)((tq+tk+255)/256),256>>>(S, tq, tq+tk);     // 5

    const int FLASH_SMEM = (64*130*2 + 64*65)*4;  // 83200 bytes
    cudaFuncSetAttribute(flash_kernel, cudaFuncAttributeMaxDynamicSharedMemorySize, FLASH_SMEM);
    flash_kernel<<<dim3(S/64, B*HEADS),256,FLASH_SMEM>>>(mask, S);          // 6 <- profiled

    act_quant_kernel<<<M,256>>>(no_, 3);                                    // 7
    imma_o_kernel<<<dim3(HDIM/64, M/128),256>>>(S, out);                    // 8
}